// round 1
// baseline (speedup 1.0000x reference)
#include <cuda_runtime.h>
#include <cstdint>

// Problem constants (fixed by setup_inputs): B=2, N=256, D=256, H=8, LEN=516
#define B_      2
#define N_      256
#define D_      256
#define H_      8
#define ITEMS_  (B_ * N_ * N_)     // 131072
#define LEN_    (2 * D_ + 4)       // 516
#define EPS_    1e-8f

typedef unsigned long long u64;

// scratch (device globals; no allocation allowed)
__device__ float g_scores[ITEMS_];
__device__ float g_ind[N_];

// ---------- packed f32x2 helpers (sm_103a) ----------
__device__ __forceinline__ u64 ffma2(u64 a, u64 b, u64 c) {
    u64 d;
    asm("fma.rn.f32x2 %0, %1, %2, %3;" : "=l"(d) : "l"(a), "l"(b), "l"(c));
    return d;
}
__device__ __forceinline__ float hadd2(u64 v) {
    float lo, hi;
    asm("mov.b64 {%0, %1}, %2;" : "=f"(lo), "=f"(hi) : "l"(v));
    return lo + hi;
}

// ============================================================================
// Kernel 1 (fused): one warp per item (b,q,k).
//   - lane l covers channels c in {4l..4l+3} u {128+4l..128+4l+3}
//   - per-head linear partials + q.k / q.q / k.k partials, packed f32x2
//   - weights register-resident (129 floats/lane), loaded once per block
//   - butterfly-reduce 11 values; lanes 0..7 write sigmoid(head)*roi to out,
//     lane 8 writes relu(cosine) score to g_scores
// ============================================================================
__global__ __launch_bounds__(256, 1)
void fused_main(const float* __restrict__ q, const float* __restrict__ k,
                const float* __restrict__ sq, const float* __restrict__ sk,
                const float* __restrict__ roi, const float* __restrict__ W,
                const float* __restrict__ bias, float* __restrict__ out)
{
    const int lane   = threadIdx.x & 31;
    const int warp   = blockIdx.x * (blockDim.x >> 5) + (threadIdx.x >> 5);
    const int nwarps = gridDim.x * (blockDim.x >> 5);

    // ---- load per-lane weights into registers (once per block) ----
    u64 wq[H_][4], wk[H_][4];
#pragma unroll
    for (int h = 0; h < H_; h++) {
        const float* wr = W + h * LEN_ + 4 * lane;   // row start h*2064B is 16B aligned
        ulonglong2 t0 = *(const ulonglong2*)(wr);
        ulonglong2 t1 = *(const ulonglong2*)(wr + 128);
        ulonglong2 t2 = *(const ulonglong2*)(wr + 256);
        ulonglong2 t3 = *(const ulonglong2*)(wr + 384);
        wq[h][0] = t0.x; wq[h][1] = t0.y; wq[h][2] = t1.x; wq[h][3] = t1.y;
        wk[h][0] = t2.x; wk[h][1] = t2.y; wk[h][2] = t3.x; wk[h][3] = t3.y;
    }
    // spatial weights + bias: lane h (h<8) owns head h's tail weights
    float ws0 = 0.f, ws1 = 0.f, ws2 = 0.f, ws3 = 0.f, bb = 0.f;
    if (lane < H_) {
        const float* wr = W + lane * LEN_ + 512;
        float4 s4 = *(const float4*)wr;
        ws0 = s4.x; ws1 = s4.y; ws2 = s4.z; ws3 = s4.w;
        bb = bias[lane];
    }

    int i = warp;
    ulonglong2 q0, q1, k0, k1;
    if (i < ITEMS_) {
        const float* qp = q + (size_t)i * D_ + 4 * lane;
        const float* kp = k + (size_t)i * D_ + 4 * lane;
        q0 = *(const ulonglong2*)qp;  q1 = *(const ulonglong2*)(qp + 128);
        k0 = *(const ulonglong2*)kp;  k1 = *(const ulonglong2*)(kp + 128);
    }

    while (i < ITEMS_) {
        const int inext = i + nwarps;
        // ---- depth-1 prefetch of next item's q/k tiles ----
        ulonglong2 nq0, nq1, nk0, nk1;
        nq0.x = nq0.y = 0ull; nq1 = nq0; nk0 = nq0; nk1 = nq0;
        if (inext < ITEMS_) {
            const float* qp = q + (size_t)inext * D_ + 4 * lane;
            const float* kp = k + (size_t)inext * D_ + 4 * lane;
            nq0 = *(const ulonglong2*)qp;  nq1 = *(const ulonglong2*)(qp + 128);
            nk0 = *(const ulonglong2*)kp;  nk1 = *(const ulonglong2*)(kp + 128);
        }

        const float rmask = roi[i];
        float2 sqv = make_float2(0.f, 0.f), skv = make_float2(0.f, 0.f);
        if (lane < H_) {
            sqv = *(const float2*)(sq + (size_t)i * 2);
            skv = *(const float2*)(sk + (size_t)i * 2);
        }

        const u64 qd0 = q0.x, qd1 = q0.y, qd2 = q1.x, qd3 = q1.y;
        const u64 kd0 = k0.x, kd1 = k0.y, kd2 = k1.x, kd3 = k1.y;

        float v[11];
        // head linear partials (8 ffma2 each, 8 independent chains for ILP)
#pragma unroll
        for (int h = 0; h < H_; h++) {
            u64 a = ffma2(qd0, wq[h][0], 0ull);
            a = ffma2(qd1, wq[h][1], a);
            a = ffma2(qd2, wq[h][2], a);
            a = ffma2(qd3, wq[h][3], a);
            a = ffma2(kd0, wk[h][0], a);
            a = ffma2(kd1, wk[h][1], a);
            a = ffma2(kd2, wk[h][2], a);
            a = ffma2(kd3, wk[h][3], a);
            v[h] = hadd2(a);
        }
        // cosine partials
        {
            u64 aqk = ffma2(qd0, kd0, 0ull);
            u64 aqq = ffma2(qd0, qd0, 0ull);
            u64 akk = ffma2(kd0, kd0, 0ull);
            aqk = ffma2(qd1, kd1, aqk); aqq = ffma2(qd1, qd1, aqq); akk = ffma2(kd1, kd1, akk);
            aqk = ffma2(qd2, kd2, aqk); aqq = ffma2(qd2, qd2, aqq); akk = ffma2(kd2, kd2, akk);
            aqk = ffma2(qd3, kd3, aqk); aqq = ffma2(qd3, qd3, aqq); akk = ffma2(kd3, kd3, akk);
            v[8] = hadd2(aqk); v[9] = hadd2(aqq); v[10] = hadd2(akk);
        }
        // butterfly reduce all 11 values across the warp
#pragma unroll
        for (int j = 0; j < 11; j++) {
#pragma unroll
            for (int o = 16; o > 0; o >>= 1)
                v[j] += __shfl_xor_sync(0xffffffffu, v[j], o);
        }

        if (lane < H_) {
            float pre = v[0];
            if (lane == 1) pre = v[1];
            if (lane == 2) pre = v[2];
            if (lane == 3) pre = v[3];
            if (lane == 4) pre = v[4];
            if (lane == 5) pre = v[5];
            if (lane == 6) pre = v[6];
            if (lane == 7) pre = v[7];
            pre += sqv.x * ws0 + sqv.y * ws1 + skv.x * ws2 + skv.y * ws3 + bb;
            const float sig = 1.0f / (1.0f + __expf(-pre));
            out[(size_t)i * H_ + lane] = sig * rmask;
        } else if (lane == 8) {
            const float qn = fmaxf(sqrtf(v[9]),  EPS_);
            const float kn = fmaxf(sqrtf(v[10]), EPS_);
            const float sc = v[8] / (qn * kn);
            g_scores[i] = fmaxf(sc, 0.0f);
        }

        q0 = nq0; q1 = nq1; k0 = nk0; k1 = nk1;
        i = inext;
    }
}

// ============================================================================
// Kernel 2a: zero the indicator
// ============================================================================
__global__ void zero_ind()
{
    if (threadIdx.x < N_) g_ind[threadIdx.x] = 0.0f;
}

// ============================================================================
// Kernel 2b: exact top-k membership per row (jax.lax.top_k tie semantics:
// rank = #{j: s_j > s_t} + #{j < t: s_j == s_t}; selected iff rank < node_num).
// Union over all rows -> g_ind. One block per (b,q) row.
// ============================================================================
__global__ void mark_topk(const int* __restrict__ node_num_p)
{
    __shared__ float s[N_];
    const int row = blockIdx.x;
    const int t   = threadIdx.x;
    const int nn  = *node_num_p;

    const float mine = g_scores[row * N_ + t];
    s[t] = mine;
    __syncthreads();

    int rank = 0;
#pragma unroll 8
    for (int j = 0; j < N_; j++) {
        const float o = s[j];
        rank += (o > mine) || ((j < t) && (o == mine));
    }
    if (rank < nn) g_ind[t] = 1.0f;   // benign race: all writers store 1.0f
}

// ============================================================================
// Kernel 3: out[b,q,k,h] *= ind[k]   (vectorized float4; 2 float4 per item)
// ============================================================================
__global__ void apply_ind(float* __restrict__ out)
{
    const int idx  = blockIdx.x * blockDim.x + threadIdx.x;  // float4 index
    const int item = idx >> 1;
    const int col  = item & (N_ - 1);
    const float m  = g_ind[col];
    float4* o4 = (float4*)out;
    float4 v = o4[idx];
    v.x *= m; v.y *= m; v.z *= m; v.w *= m;
    o4[idx] = v;
}

// ============================================================================
extern "C" void kernel_launch(void* const* d_in, const int* in_sizes, int n_in,
                              void* d_out, int out_size)
{
    const float* q   = (const float*)d_in[0];
    const float* k   = (const float*)d_in[1];
    const float* sq  = (const float*)d_in[2];
    const float* sk  = (const float*)d_in[3];
    const float* roi = (const float*)d_in[4];
    const float* W   = (const float*)d_in[5];
    const float* b   = (const float*)d_in[6];
    const int*   nn  = (const int*)d_in[7];
    float* out = (float*)d_out;

    fused_main<<<592, 256>>>(q, k, sq, sk, roi, W, b, out);
    zero_ind<<<1, 256>>>();
    mark_topk<<<B_ * N_, N_>>>(nn);
    apply_ind<<<(ITEMS_ * H_ / 4) / 256, 256>>>(out);
}

// round 2
// speedup vs baseline: 1.0939x; 1.0939x over previous
#include <cuda_runtime.h>
#include <cstdint>

// Problem constants (fixed by setup_inputs): B=2, N=256, D=256, H=8, LEN=516
#define B_      2
#define N_      256
#define D_      256
#define H_      8
#define ITEMS_  (B_ * N_ * N_)     // 131072
#define LEN_    (2 * D_ + 4)       // 516
#define EPS_    1e-8f
#define TILE_   32
#define NTILES_ (ITEMS_ / TILE_)   // 4096
#define NTHR_   256

typedef unsigned long long u64;

// ---------------- device-global scratch (no allocation allowed) -------------
__device__ float      g_scores[ITEMS_];
__device__ float      g_ind[N_];
// packed weights: [group g(64)][head h(8)][wq0 wq1 wq2 wq3 wk0 wk1 wk2 wk3]
__device__ ulonglong2 g_w64[64 * 8 * 2];   // 4096 floats = 16KB
__device__ float      g_wtail[H_ * 4];     // W[h][512..515]
__device__ float      g_bias[H_];

// ---------------- packed f32x2 helpers (sm_103a) ----------------------------
__device__ __forceinline__ u64 ffma2(u64 a, u64 b, u64 c) {
    u64 d;
    asm("fma.rn.f32x2 %0, %1, %2, %3;" : "=l"(d) : "l"(a), "l"(b), "l"(c));
    return d;
}
__device__ __forceinline__ float hadd2(u64 v) {
    float lo, hi;
    asm("mov.b64 {%0, %1}, %2;" : "=f"(lo), "=f"(hi) : "l"(v));
    return lo + hi;
}

// ============================================================================
// Kernel 0: repack weights into broadcast-friendly layout (runs every launch,
// deterministic & idempotent).
// ============================================================================
__global__ void reorg_w(const float* __restrict__ W, const float* __restrict__ b)
{
    const int idx = blockIdx.x * NTHR_ + threadIdx.x;   // 0..4095
    if (idx < 4096) {
        const int g = idx >> 6;         // 0..63
        const int h = (idx >> 3) & 7;   // 0..7
        const int c = idx & 7;          // 0..7
        float v = (c < 4) ? W[h * LEN_ + 4 * g + c]
                          : W[h * LEN_ + 256 + 4 * g + (c - 4)];
        ((float*)g_w64)[idx] = v;
    }
    if (idx < H_ * 4) {
        const int h = idx >> 2, c = idx & 3;
        g_wtail[idx] = W[h * LEN_ + 512 + c];
    }
    if (idx < H_) g_bias[idx] = b[idx];
}

// ============================================================================
// Kernel 1 (fused): lane-per-item, smem-staged tiles of 32 items.
//   Per tile: two phases (channels 0..127, 128..255 of both q and k).
//   Each phase stages 32 items x (32 q-chunks + 32 k-chunks) float4 into smem
//   (row stride 65 chunks -> odd -> conflict-free LDS.128, lane = item).
//   Warp w accumulates groups {w*4..w*4+3} per phase into 11 per-lane packed
//   accumulators (8 heads + qk,qq,kk). No cross-lane shuffles.
//   Epilogue: cross-warp combine via smem partials; warp h finishes head h,
//   warp 0 additionally finishes the cosine score.
// ============================================================================
__device__ __forceinline__ void compute_phase(u64 acc[11], const ulonglong2* dat,
                                              int phase, int w, int lane)
{
#pragma unroll
    for (int j = 0; j < 4; j++) {
        const int cq = w * 4 + j;                       // q chunk col 0..31
        const ulonglong2 qd = dat[lane * 65 + cq];
        const ulonglong2 kd = dat[lane * 65 + 32 + cq];
        const int g = phase * 32 + cq;                  // global 4-ch group
        const ulonglong2* wp = g_w64 + g * 16;
#pragma unroll
        for (int h = 0; h < H_; h++) {
            const ulonglong2 wq = __ldg(wp + h * 2);
            const ulonglong2 wk = __ldg(wp + h * 2 + 1);
            acc[h] = ffma2(qd.x, wq.x, acc[h]);
            acc[h] = ffma2(qd.y, wq.y, acc[h]);
            acc[h] = ffma2(kd.x, wk.x, acc[h]);
            acc[h] = ffma2(kd.y, wk.y, acc[h]);
        }
        acc[8]  = ffma2(qd.x, kd.x, acc[8]);
        acc[8]  = ffma2(qd.y, kd.y, acc[8]);
        acc[9]  = ffma2(qd.x, qd.x, acc[9]);
        acc[9]  = ffma2(qd.y, qd.y, acc[9]);
        acc[10] = ffma2(kd.x, kd.x, acc[10]);
        acc[10] = ffma2(kd.y, kd.y, acc[10]);
    }
}

__device__ __forceinline__ void prefetch_tile(ulonglong2 pf[8],
                                              const ulonglong2* __restrict__ q2,
                                              const ulonglong2* __restrict__ k2,
                                              int tile, int phase, int t)
{
#pragma unroll
    for (int j = 0; j < 8; j++) {
        const int idx  = j * NTHR_ + t;     // 0..2047
        const int item = idx >> 6;          // 0..31
        const int c    = idx & 63;          // 0..63
        const long base = ((long)(tile * TILE_ + item)) * 64 + phase * 32;
        pf[j] = (c < 32) ? __ldg(q2 + base + c) : __ldg(k2 + base + (c - 32));
    }
}

__global__ __launch_bounds__(NTHR_, 2)
void fused_main(const ulonglong2* __restrict__ q2, const ulonglong2* __restrict__ k2,
                const float2* __restrict__ sq2, const float2* __restrict__ sk2,
                const float* __restrict__ roi, float4* __restrict__ out4)
{
    __shared__ ulonglong2 data_s[TILE_ * 65];   // 33,280 B
    __shared__ float      part_s[11][8][32];    // 11,264 B
    __shared__ float4     out_s[TILE_ * 2];     //  1,024 B

    const int t    = threadIdx.x;
    const int w    = t >> 5;
    const int lane = t & 31;
    const int stride = gridDim.x;

    ulonglong2 pf[8];
    int tile = blockIdx.x;
    prefetch_tile(pf, q2, k2, tile, 0, t);      // first tile, phase 0

    for (; tile < NTILES_; tile += stride) {
        u64 acc[11];
#pragma unroll
        for (int v = 0; v < 11; v++) acc[v] = 0ull;

        // ---------------- phase 0 ----------------
        __syncthreads();                         // data_s free to overwrite
#pragma unroll
        for (int j = 0; j < 8; j++) {
            const int idx = j * NTHR_ + t;
            data_s[(idx >> 6) * 65 + (idx & 63)] = pf[j];
        }
        prefetch_tile(pf, q2, k2, tile, 1, t);   // phase 1 in flight
        __syncthreads();
        compute_phase(acc, data_s, 0, w, lane);

        // ---------------- phase 1 ----------------
        __syncthreads();
#pragma unroll
        for (int j = 0; j < 8; j++) {
            const int idx = j * NTHR_ + t;
            data_s[(idx >> 6) * 65 + (idx & 63)] = pf[j];
        }
        {   // next tile's phase 0 in flight
            const int ntile = tile + stride;
            if (ntile < NTILES_) prefetch_tile(pf, q2, k2, ntile, 0, t);
        }
        __syncthreads();
        compute_phase(acc, data_s, 1, w, lane);

        // ---------------- partials ----------------
#pragma unroll
        for (int v = 0; v < 11; v++) part_s[v][w][lane] = hadd2(acc[v]);
        __syncthreads();

        // ---------------- epilogue ----------------
        const int item_g = tile * TILE_ + lane;
        {
            // warp w finishes head h = w for all 32 items (lane = item)
            float s = 0.f;
#pragma unroll
            for (int w2 = 0; w2 < 8; w2++) s += part_s[w][w2][lane];
            const float4 wt = *(const float4*)(g_wtail + w * 4);
            const float2 a  = __ldg(sq2 + item_g);
            const float2 bb = __ldg(sk2 + item_g);
            const float pre = s + a.x * wt.x + a.y * wt.y
                                + bb.x * wt.z + bb.y * wt.w + g_bias[w];
            const float sig = 1.0f / (1.0f + __expf(-pre));
            const float r   = __ldg(roi + item_g);
            ((float*)out_s)[lane * H_ + w] = sig * r;
        }
        if (w == 0) {
            float qk = 0.f, qq = 0.f, kk = 0.f;
#pragma unroll
            for (int w2 = 0; w2 < 8; w2++) {
                qk += part_s[8][w2][lane];
                qq += part_s[9][w2][lane];
                kk += part_s[10][w2][lane];
            }
            const float qn = fmaxf(sqrtf(qq), EPS_);
            const float kn = fmaxf(sqrtf(kk), EPS_);
            g_scores[item_g] = fmaxf(qk / (qn * kn), 0.0f);
        }
        __syncthreads();
        if (t < 64) out4[tile * 64 + t] = out_s[t];   // coalesced 1KB store
    }
}

// ============================================================================
// Kernel 2a: zero the indicator
// ============================================================================
__global__ void zero_ind()
{
    if (threadIdx.x < N_) g_ind[threadIdx.x] = 0.0f;
}

// ============================================================================
// Kernel 2b: exact top-k membership per row (jax.lax.top_k tie semantics:
// rank = #{j: s_j > s_t} + #{j < t: s_j == s_t}; selected iff rank < node_num).
// Union over all rows -> g_ind. One block per (b,q) row.
// ============================================================================
__global__ void mark_topk(const int* __restrict__ node_num_p)
{
    __shared__ float s[N_];
    const int row = blockIdx.x;
    const int t   = threadIdx.x;
    const int nn  = *node_num_p;

    const float mine = g_scores[row * N_ + t];
    s[t] = mine;
    __syncthreads();

    int rank = 0;
#pragma unroll 8
    for (int j = 0; j < N_; j++) {
        const float o = s[j];
        rank += (o > mine) || ((j < t) && (o == mine));
    }
    if (rank < nn) g_ind[t] = 1.0f;   // benign race: all writers store 1.0f
}

// ============================================================================
// Kernel 3: out[b,q,k,h] *= ind[k]   (2 float4 per thread, fully coalesced)
// ============================================================================
__global__ void apply_ind(float4* __restrict__ out4)
{
    const int idx = blockIdx.x * blockDim.x + threadIdx.x;  // 0..131071
#pragma unroll
    for (int rep = 0; rep < 2; rep++) {
        const int i4   = rep * (ITEMS_ * H_ / 8) + idx;     // float4 index
        const int item = i4 >> 1;
        const int col  = item & (N_ - 1);
        const float m  = g_ind[col];
        float4 v = out4[i4];
        v.x *= m; v.y *= m; v.z *= m; v.w *= m;
        out4[i4] = v;
    }
}

// ============================================================================
extern "C" void kernel_launch(void* const* d_in, const int* in_sizes, int n_in,
                              void* d_out, int out_size)
{
    (void)in_sizes; (void)n_in; (void)out_size;
    const ulonglong2* q2  = (const ulonglong2*)d_in[0];
    const ulonglong2* k2  = (const ulonglong2*)d_in[1];
    const float2*     sq  = (const float2*)d_in[2];
    const float2*     sk  = (const float2*)d_in[3];
    const float*      roi = (const float*)d_in[4];
    const float*      W   = (const float*)d_in[5];
    const float*      b   = (const float*)d_in[6];
    const int*        nn  = (const int*)d_in[7];
    float4* out4 = (float4*)d_out;

    reorg_w<<<16, NTHR_>>>(W, b);
    fused_main<<<296, NTHR_>>>(q2, k2, sq, sk, roi, out4);
    zero_ind<<<1, NTHR_>>>();
    mark_topk<<<B_ * N_, N_>>>(nn);
    apply_ind<<<(ITEMS_ * H_ / 8) / NTHR_, NTHR_>>>(out4);
}

// round 3
// speedup vs baseline: 1.7424x; 1.5929x over previous
#include <cuda_runtime.h>
#include <cstdint>

// Problem constants (fixed by setup_inputs): B=2, N=256, D=256, H=8, LEN=516
#define B_      2
#define N_      256
#define H_      8
#define ITEMS_  131072
#define LEN_    516
#define EPS_    1e-8f
#define TILE_   64
#define NTILES_ (ITEMS_ / TILE_)   // 2048
#define GRID_   152                // GB300 SM count, 1 persistent CTA/SM

typedef unsigned long long u64;

// ---------------- device-global scratch (no allocation allowed) -------------
__device__ float      g_scores[ITEMS_];
__device__ float      g_ind[N_];
// packed weights: [group g(64)][head h(8)][wq0..wq3, wk0..wk3]
__device__ ulonglong2 g_w64[64 * 8 * 2];   // 4096 floats = 16KB
__device__ float      g_wtail[H_ * 4];
__device__ float      g_bias[H_];

// dynamic smem layout (ulonglong2 units where noted):
//   buf0 [64*65] u128, buf1 [64*65] u128, wbuf [1024] u128,
//   part [11][16][64] f32, outs [512] f32, wts [40] f32
#define SMEM_TOTAL ((2 * 64 * 65 + 1024) * 16 + 11 * 16 * 64 * 4 + 512 * 4 + 40 * 4)

// ---------------- packed f32x2 helpers (sm_103a) ----------------------------
__device__ __forceinline__ u64 ffma2(u64 a, u64 b, u64 c) {
    u64 d;
    asm("fma.rn.f32x2 %0, %1, %2, %3;" : "=l"(d) : "l"(a), "l"(b), "l"(c));
    return d;
}
__device__ __forceinline__ float hadd2(u64 v) {
    float lo, hi;
    asm("mov.b64 {%0, %1}, %2;" : "=f"(lo), "=f"(hi) : "l"(v));
    return lo + hi;
}

// ============================================================================
// Kernel 0: repack weights (idempotent, runs every launch)
// ============================================================================
__global__ void reorg_w(const float* __restrict__ W, const float* __restrict__ b)
{
    const int idx = blockIdx.x * 256 + threadIdx.x;   // 0..4095
    if (idx < 4096) {
        const int g = idx >> 6;         // 0..63
        const int h = (idx >> 3) & 7;   // 0..7
        const int c = idx & 7;          // 0..7
        float v = (c < 4) ? W[h * LEN_ + 4 * g + c]
                          : W[h * LEN_ + 256 + 4 * g + (c - 4)];
        ((float*)g_w64)[idx] = v;
    }
    if (idx < H_ * 4) {
        const int h = idx >> 2, c = idx & 3;
        g_wtail[idx] = W[h * LEN_ + 512 + c];
    }
    if (idx < H_) g_bias[idx] = b[idx];
}

// ============================================================================
// cp.async 16B helper — bypasses L1, lands directly in smem
// ============================================================================
__device__ __forceinline__ void docopy(uint32_t bad, const ulonglong2* sbase,
                                       long tile, int p, int r0, int col,
                                       uint32_t dcon)
{
    // src element index: tile*4096 + (j*8+r0)*64 + p*32 + col
    const ulonglong2* s = sbase + (tile << 12) + (long)p * 32 + (long)r0 * 64 + col;
    uint32_t d = bad + dcon;
#pragma unroll
    for (int j = 0; j < 8; j++) {
        asm volatile("cp.async.cg.shared.global [%0], [%1], 16;" :: "r"(d), "l"(s));
        s += 512;            // 8 items * 64 chunks
        d += 8 * 65 * 16;    // 8 items * padded row
    }
}

// ============================================================================
// Kernel 1 (fused): persistent CTAs, TILE=64 items, 512 threads (16 warps).
//   Phase p covers channels [p*128, p*128+128) of q and k.
//   cp.async double-buffers the two phases; weights live in smem (broadcast
//   LDS); lane handles items (lane) and (lane+32) -> 22 packed accumulators;
//   warp w covers chunk-groups {2w, 2w+1} of each phase.
// ============================================================================
__global__ __launch_bounds__(512, 1)
void fused_main(const ulonglong2* __restrict__ q2, const ulonglong2* __restrict__ k2,
                const float2* __restrict__ sq2, const float2* __restrict__ sk2,
                const float* __restrict__ roi, float4* __restrict__ out4)
{
    extern __shared__ ulonglong2 smem[];
    ulonglong2* buf0 = smem;
    ulonglong2* buf1 = smem + 64 * 65;
    ulonglong2* wbuf = smem + 2 * 64 * 65;            // 1024 entries (16KB)
    float* part = (float*)(wbuf + 1024);              // [11][16][64]
    float* outs = part + 11 * 16 * 64;                // 512 floats
    float* wts  = outs + 512;                         // 32 tail + 8 bias

    const int t    = threadIdx.x;
    const int w    = t >> 5;
    const int lane = t & 31;

    // stage weights into smem once
    for (int i = t; i < 1024; i += 512) wbuf[i] = g_w64[i];
    if (t < 32) wts[t]      = g_wtail[t];
    if (t < 8)  wts[32 + t] = g_bias[t];

    // copy-geometry constants (per thread)
    const int r0  = t >> 6;        // 0..7
    const int c   = t & 63;        // 0..63  (chunk column; <32 -> q, else k)
    const int col = c & 31;
    const ulonglong2* sbase = (c < 32) ? q2 : k2;
    const uint32_t dcon = (uint32_t)((r0 * 65 + c) * sizeof(ulonglong2));
    const uint32_t b0a = (uint32_t)__cvta_generic_to_shared(buf0);
    const uint32_t b1a = (uint32_t)__cvta_generic_to_shared(buf1);

    u64 acc[22];

    auto compute = [&](const ulonglong2* __restrict__ bp, int p) {
        const ulonglong2* da = bp + lane * 65;
        const ulonglong2* db = bp + (lane + 32) * 65;
#pragma unroll
        for (int j = 0; j < 2; j++) {
            const int cq = w * 2 + j;
            const ulonglong2 qa = da[cq],      ka = da[32 + cq];
            const ulonglong2 qb = db[cq],      kb = db[32 + cq];
            const ulonglong2* wp = wbuf + (p * 32 + cq) * 16;
#pragma unroll
            for (int h = 0; h < 8; h++) {
                const ulonglong2 wq = wp[h * 2];
                const ulonglong2 wk = wp[h * 2 + 1];
                acc[h] = ffma2(qa.x, wq.x, acc[h]);
                acc[h] = ffma2(qa.y, wq.y, acc[h]);
                acc[h] = ffma2(ka.x, wk.x, acc[h]);
                acc[h] = ffma2(ka.y, wk.y, acc[h]);
                acc[11 + h] = ffma2(qb.x, wq.x, acc[11 + h]);
                acc[11 + h] = ffma2(qb.y, wq.y, acc[11 + h]);
                acc[11 + h] = ffma2(kb.x, wk.x, acc[11 + h]);
                acc[11 + h] = ffma2(kb.y, wk.y, acc[11 + h]);
            }
            acc[8]  = ffma2(qa.x, ka.x, acc[8]);  acc[8]  = ffma2(qa.y, ka.y, acc[8]);
            acc[9]  = ffma2(qa.x, qa.x, acc[9]);  acc[9]  = ffma2(qa.y, qa.y, acc[9]);
            acc[10] = ffma2(ka.x, ka.x, acc[10]); acc[10] = ffma2(ka.y, ka.y, acc[10]);
            acc[19] = ffma2(qb.x, kb.x, acc[19]); acc[19] = ffma2(qb.y, kb.y, acc[19]);
            acc[20] = ffma2(qb.x, qb.x, acc[20]); acc[20] = ffma2(qb.y, qb.y, acc[20]);
            acc[21] = ffma2(kb.x, kb.x, acc[21]); acc[21] = ffma2(kb.y, kb.y, acc[21]);
        }
    };

    long tile = blockIdx.x;
    if (tile < NTILES_) docopy(b0a, sbase, tile, 0, r0, col, dcon);
    asm volatile("cp.async.commit_group;");
    if (tile < NTILES_) docopy(b1a, sbase, tile, 1, r0, col, dcon);
    asm volatile("cp.async.commit_group;");

    for (; tile < NTILES_; tile += GRID_) {
        const long tn = tile + GRID_;
#pragma unroll
        for (int v = 0; v < 22; v++) acc[v] = 0ull;

        // ---- phase 0 ----
        asm volatile("cp.async.wait_group 1;");
        __syncthreads();                              // buf0 ready & visible
        compute(buf0, 0);
        __syncthreads();                              // all done reading buf0
        if (tn < NTILES_) docopy(b0a, sbase, tn, 0, r0, col, dcon);
        asm volatile("cp.async.commit_group;");

        // ---- phase 1 ----
        asm volatile("cp.async.wait_group 1;");
        __syncthreads();                              // buf1 ready & visible
        compute(buf1, 1);

        // ---- partials ----
#pragma unroll
        for (int v = 0; v < 11; v++) {
            part[(v * 16 + w) * 64 + lane]      = hadd2(acc[v]);
            part[(v * 16 + w) * 64 + 32 + lane] = hadd2(acc[11 + v]);
        }
        __syncthreads();                              // buf1 free + parts visible
        if (tn < NTILES_) docopy(b1a, sbase, tn, 1, r0, col, dcon);
        asm volatile("cp.async.commit_group;");

        // ---- epilogue: heads (all 512 threads: h = t>>6, item = t&63) ----
        {
            const int h = t >> 6, it = t & 63;
            float s = 0.f;
#pragma unroll
            for (int w2 = 0; w2 < 16; w2++) s += part[(h * 16 + w2) * 64 + it];
            const int ig = (int)tile * 64 + it;
            const float4 wt = *(const float4*)(wts + h * 4);
            const float2 a  = sq2[ig];
            const float2 bb = sk2[ig];
            const float pre = s + a.x * wt.x + a.y * wt.y
                                + bb.x * wt.z + bb.y * wt.w + wts[32 + h];
            outs[it * 8 + h] = (1.0f / (1.0f + __expf(-pre))) * roi[ig];
        }
        // ---- epilogue: cosine (threads 0..63, item = t) ----
        if (t < 64) {
            float qk = 0.f, qq = 0.f, kk = 0.f;
#pragma unroll
            for (int w2 = 0; w2 < 16; w2++) {
                qk += part[(8  * 16 + w2) * 64 + t];
                qq += part[(9  * 16 + w2) * 64 + t];
                kk += part[(10 * 16 + w2) * 64 + t];
            }
            const float qn = fmaxf(sqrtf(qq), EPS_);
            const float kn = fmaxf(sqrtf(kk), EPS_);
            g_scores[(int)tile * 64 + t] = fmaxf(qk / (qn * kn), 0.0f);
        }
        __syncthreads();                              // outs ready
        if (t < 128) out4[tile * 128 + t] = ((const float4*)outs)[t];
    }
}

// ============================================================================
// Kernel 2a: zero the indicator
// ============================================================================
__global__ void zero_ind()
{
    if (threadIdx.x < N_) g_ind[threadIdx.x] = 0.0f;
}

// ============================================================================
// Kernel 2b: top-k membership, split-loop form (tie term folded into >=):
//   rank = #{j<t: s_j >= s_t} + #{j>t: s_j > s_t};  selected iff rank < nn.
// ============================================================================
__global__ void mark_topk(const int* __restrict__ node_num_p)
{
    __shared__ float s[N_];
    const int row = blockIdx.x;
    const int t   = threadIdx.x;
    const int nn  = *node_num_p;

    const float mine = g_scores[row * N_ + t];
    s[t] = mine;
    __syncthreads();

    int rank = 0;
#pragma unroll 4
    for (int j = 0; j < t; j++)        rank += (s[j] >= mine);
#pragma unroll 4
    for (int j = t + 1; j < N_; j++)   rank += (s[j] >  mine);
    if (rank < nn) g_ind[t] = 1.0f;   // benign race: all writers store 1.0f
}

// ============================================================================
// Kernel 3: out[b,q,k,h] *= ind[k]   (one float4 per thread, coalesced)
// ============================================================================
__global__ void apply_ind(float4* __restrict__ out4)
{
    const int i4   = blockIdx.x * blockDim.x + threadIdx.x;  // 0..262143
    const int col  = (i4 >> 1) & (N_ - 1);
    const float m  = g_ind[col];
    float4 v = out4[i4];
    v.x *= m; v.y *= m; v.z *= m; v.w *= m;
    out4[i4] = v;
}

// ============================================================================
extern "C" void kernel_launch(void* const* d_in, const int* in_sizes, int n_in,
                              void* d_out, int out_size)
{
    (void)in_sizes; (void)n_in; (void)out_size;
    const ulonglong2* q2  = (const ulonglong2*)d_in[0];
    const ulonglong2* k2  = (const ulonglong2*)d_in[1];
    const float2*     sq  = (const float2*)d_in[2];
    const float2*     sk  = (const float2*)d_in[3];
    const float*      roi = (const float*)d_in[4];
    const float*      W   = (const float*)d_in[5];
    const float*      b   = (const float*)d_in[6];
    const int*        nn  = (const int*)d_in[7];
    float4* out4 = (float4*)d_out;

    cudaFuncSetAttribute(fused_main, cudaFuncAttributeMaxDynamicSharedMemorySize,
                         SMEM_TOTAL);

    reorg_w<<<16, 256>>>(W, b);
    fused_main<<<GRID_, 512, SMEM_TOTAL>>>(q2, k2, sq, sk, roi, out4);
    zero_ind<<<1, 256>>>();
    mark_topk<<<B_ * N_, N_>>>(nn);
    apply_ind<<<(ITEMS_ * H_ / 4) / 256, 256>>>(out4);
}

// round 4
// speedup vs baseline: 1.9177x; 1.1006x over previous
#include <cuda_runtime.h>
#include <cstdint>

// Problem constants (fixed by setup_inputs): B=2, N=256, D=256, H=8, LEN=516
#define B_      2
#define N_      256
#define H_      8
#define ITEMS_  131072
#define LEN_    516
#define EPS_    1e-8f
#define TILE_   64
#define NTILES_ (ITEMS_ / TILE_)   // 2048
#define GRID_   152                // GB300 SM count, 1 persistent CTA/SM

typedef unsigned long long u64;

// ---------------- device-global scratch (no allocation allowed) -------------
__device__ float      g_scores[ITEMS_];
__device__ float      g_ind[N_];
// packed weights: [group g(64)][head h(8)][wq0..wq3, wk0..wk3]
__device__ ulonglong2 g_w64[64 * 8 * 2];   // 4096 floats = 16KB
__device__ float      g_wtail[H_ * 4];
__device__ float      g_bias[H_];

// dynamic smem: 4 stage-buffers [64 items x 33 chunks] u128, wbuf 1024 u128,
// part [11][16][64] f32, outs 512 f32, wts 40 f32
#define BUFCH_      (64 * 33)
#define SMEM_TOTAL  ((4 * BUFCH_ + 1024) * 16 + 11 * 16 * 64 * 4 + 512 * 4 + 40 * 4)

// ---------------- packed f32x2 helpers (sm_103a) ----------------------------
__device__ __forceinline__ u64 ffma2(u64 a, u64 b, u64 c) {
    u64 d;
    asm("fma.rn.f32x2 %0, %1, %2, %3;" : "=l"(d) : "l"(a), "l"(b), "l"(c));
    return d;
}
__device__ __forceinline__ float hadd2(u64 v) {
    float lo, hi;
    asm("mov.b64 {%0, %1}, %2;" : "=f"(lo), "=f"(hi) : "l"(v));
    return lo + hi;
}

// ============================================================================
// Kernel 0: repack weights + zero indicator (idempotent, runs every launch)
// ============================================================================
__global__ void reorg_w(const float* __restrict__ W, const float* __restrict__ b)
{
    const int idx = blockIdx.x * 256 + threadIdx.x;   // 0..4095
    if (idx < 4096) {
        const int g = idx >> 6;
        const int h = (idx >> 3) & 7;
        const int c = idx & 7;
        float v = (c < 4) ? W[h * LEN_ + 4 * g + c]
                          : W[h * LEN_ + 256 + 4 * g + (c - 4)];
        ((float*)g_w64)[idx] = v;
    }
    if (idx < H_ * 4) {
        const int h = idx >> 2, c = idx & 3;
        g_wtail[idx] = W[h * LEN_ + 512 + c];
    }
    if (idx < H_) g_bias[idx] = b[idx];
    if (idx < N_) g_ind[idx] = 0.0f;
}

// ============================================================================
// cp.async stage copy: stage s = channels [s*64, s*64+64) of q and k
//   buffer layout: item i (0..63), chunk c (0..31): c<16 -> q, else k; +1 pad
//   thread t: c = t&31 fixed, items item0 + 16j (j=0..3)
// ============================================================================
__device__ __forceinline__ void docopy(uint32_t d0, const ulonglong2* __restrict__ sb,
                                       long tile, int s, int item0, int c, int cc)
{
    const ulonglong2* src = sb + (tile * 64 + item0) * 64 + s * 16 + cc;
    uint32_t d = d0 + (uint32_t)((item0 * 33 + c) * 16);
#pragma unroll
    for (int j = 0; j < 4; j++) {
        asm volatile("cp.async.cg.shared.global [%0], [%1], 16;" :: "r"(d), "l"(src));
        src += 16 * 64;
        d   += 16 * 33 * 16;
    }
}

// ============================================================================
// Kernel 1 (fused): persistent CTAs, TILE=64, 512 threads, 4-stage pipeline.
//   Stage s: 16 q-chunks + 16 k-chunks per item; warp w owns chunk w.
//   Lane handles items (lane) and (lane+32) -> 22 packed accumulators.
// ============================================================================
__global__ __launch_bounds__(512, 1)
void fused_main(const ulonglong2* __restrict__ q2, const ulonglong2* __restrict__ k2,
                const float2* __restrict__ sq2, const float2* __restrict__ sk2,
                const float* __restrict__ roi, float4* __restrict__ out4)
{
    extern __shared__ ulonglong2 smem[];
    ulonglong2* wbuf = smem + 4 * BUFCH_;            // 1024 entries (16KB)
    float* part = (float*)(wbuf + 1024);             // [11][16][64]
    float* outs = part + 11 * 16 * 64;               // 512 floats
    float* wts  = outs + 512;                        // 32 tail + 8 bias

    const int t    = threadIdx.x;
    const int w    = t >> 5;
    const int lane = t & 31;

    // stage weights into smem once
    for (int i = t; i < 1024; i += 512) wbuf[i] = g_w64[i];
    if (t < 32) wts[t]      = g_wtail[t];
    if (t < 8)  wts[32 + t] = g_bias[t];

    // copy geometry (per thread, constant)
    const int c     = t & 31;
    const int item0 = t >> 5;
    const int cc    = c & 15;
    const ulonglong2* sb = (c < 16) ? q2 : k2;
    uint32_t bad[4];
#pragma unroll
    for (int s = 0; s < 4; s++)
        bad[s] = (uint32_t)__cvta_generic_to_shared(smem + s * BUFCH_);

    u64 acc[22];

    auto compute = [&](int s) {
        const ulonglong2* da = smem + s * BUFCH_ + lane * 33;
        const ulonglong2* db = da + 32 * 33;
        const ulonglong2 qa = da[w],      ka = da[16 + w];
        const ulonglong2 qb = db[w],      kb = db[16 + w];
        const ulonglong2* wp = wbuf + (s * 16 + w) * 16;
#pragma unroll
        for (int h = 0; h < 8; h++) {
            const ulonglong2 wq = wp[h * 2];
            const ulonglong2 wk = wp[h * 2 + 1];
            acc[h] = ffma2(qa.x, wq.x, acc[h]);
            acc[h] = ffma2(qa.y, wq.y, acc[h]);
            acc[h] = ffma2(ka.x, wk.x, acc[h]);
            acc[h] = ffma2(ka.y, wk.y, acc[h]);
            acc[11 + h] = ffma2(qb.x, wq.x, acc[11 + h]);
            acc[11 + h] = ffma2(qb.y, wq.y, acc[11 + h]);
            acc[11 + h] = ffma2(kb.x, wk.x, acc[11 + h]);
            acc[11 + h] = ffma2(kb.y, wk.y, acc[11 + h]);
        }
        acc[8]  = ffma2(qa.x, ka.x, acc[8]);  acc[8]  = ffma2(qa.y, ka.y, acc[8]);
        acc[9]  = ffma2(qa.x, qa.x, acc[9]);  acc[9]  = ffma2(qa.y, qa.y, acc[9]);
        acc[10] = ffma2(ka.x, ka.x, acc[10]); acc[10] = ffma2(ka.y, ka.y, acc[10]);
        acc[19] = ffma2(qb.x, kb.x, acc[19]); acc[19] = ffma2(qb.y, kb.y, acc[19]);
        acc[20] = ffma2(qb.x, qb.x, acc[20]); acc[20] = ffma2(qb.y, qb.y, acc[20]);
        acc[21] = ffma2(kb.x, kb.x, acc[21]); acc[21] = ffma2(kb.y, kb.y, acc[21]);
    };

    // prologue: fill 4 stage buffers with first tile's stages
    long tile = blockIdx.x;
#pragma unroll
    for (int s = 0; s < 4; s++) {
        if (tile < NTILES_) docopy(bad[s], sb, tile, s, item0, c, cc);
        asm volatile("cp.async.commit_group;");
    }

    for (; tile < NTILES_; tile += GRID_) {
        const long tn = tile + GRID_;
#pragma unroll
        for (int v = 0; v < 22; v++) acc[v] = 0ull;

#pragma unroll
        for (int s = 0; s < 4; s++) {
            asm volatile("cp.async.wait_group 3;");
            __syncthreads();                           // buffer s ready & visible
            compute(s);
            if (s == 3) {                              // publish partials with next sync
#pragma unroll
                for (int v = 0; v < 11; v++) {
                    part[(v * 16 + w) * 64 + lane]      = hadd2(acc[v]);
                    part[(v * 16 + w) * 64 + 32 + lane] = hadd2(acc[11 + v]);
                }
            }
            __syncthreads();                           // done reading buffer s
            if (tn < NTILES_) docopy(bad[s], sb, tn, s, item0, c, cc);
            asm volatile("cp.async.commit_group;");
        }

        // ---- epilogue: heads (h = t>>6, item = t&63) ----
        {
            const int h = t >> 6, it = t & 63;
            float sacc = 0.f;
#pragma unroll
            for (int w2 = 0; w2 < 16; w2++) sacc += part[(h * 16 + w2) * 64 + it];
            const int ig = (int)tile * 64 + it;
            const float4 wt = *(const float4*)(wts + h * 4);
            const float2 a  = sq2[ig];
            const float2 bb = sk2[ig];
            const float pre = sacc + a.x * wt.x + a.y * wt.y
                                   + bb.x * wt.z + bb.y * wt.w + wts[32 + h];
            outs[it * 8 + h] = (1.0f / (1.0f + __expf(-pre))) * roi[ig];
        }
        // ---- epilogue: cosine (threads 0..63) ----
        if (t < 64) {
            float qk = 0.f, qq = 0.f, kk = 0.f;
#pragma unroll
            for (int w2 = 0; w2 < 16; w2++) {
                qk += part[(8  * 16 + w2) * 64 + t];
                qq += part[(9  * 16 + w2) * 64 + t];
                kk += part[(10 * 16 + w2) * 64 + t];
            }
            const float qn = fmaxf(sqrtf(qq), EPS_);
            const float kn = fmaxf(sqrtf(kk), EPS_);
            g_scores[(int)tile * 64 + t] = fmaxf(qk / (qn * kn), 0.0f);
        }
        __syncthreads();                               // outs ready
        if (t < 128) out4[tile * 128 + t] = ((const float4*)outs)[t];
    }
}

// ============================================================================
// Kernel 2: warp-per-row exact top-k marking via 32-bit radix select.
//   Keys are relu'd scores (>=0) so float bits are monotone as uint.
//   T = nn-th largest key (with multiplicity); cnt_gt = #{key > T}.
//   Selected(t) iff key_t > T, or key_t == T and cnt_gt + #{j<t: key_j==T} < nn
//   — exactly rank = #{>} + #{==, j<t} < nn.
// ============================================================================
__global__ void mark_topk(const int* __restrict__ node_num_p)
{
    const int row  = (blockIdx.x * blockDim.x + threadIdx.x) >> 5;   // 0..511
    const int lane = threadIdx.x & 31;
    const int nn   = *node_num_p;

    const float4* rp = (const float4*)(g_scores + row * N_);
    const float4 v0 = rp[lane * 2];
    const float4 v1 = rp[lane * 2 + 1];
    unsigned key[8];
    key[0] = __float_as_uint(v0.x); key[1] = __float_as_uint(v0.y);
    key[2] = __float_as_uint(v0.z); key[3] = __float_as_uint(v0.w);
    key[4] = __float_as_uint(v1.x); key[5] = __float_as_uint(v1.y);
    key[6] = __float_as_uint(v1.z); key[7] = __float_as_uint(v1.w);

    // radix descend: find T = k-th largest (k 1-based, k=nn)
    unsigned prefix = 0, mask = 0;
    int k = nn;
#pragma unroll
    for (int b = 31; b >= 0; b--) {
        const unsigned bit = 1u << b;
        const unsigned m = mask | bit, p = prefix | bit;
        int cl = 0;
#pragma unroll
        for (int i = 0; i < 8; i++) cl += ((key[i] & m) == p);
        const int cnt = __reduce_add_sync(0xffffffffu, cl);
        if (cnt >= k) prefix = p; else k -= cnt;
        mask = m;
    }
    const unsigned T = prefix;
    const int cnt_gt = nn - k;

    // exclusive count of ties in columns before this lane's range
    int eqc = 0;
#pragma unroll
    for (int i = 0; i < 8; i++) eqc += (key[i] == T);
    int ex = eqc;
#pragma unroll
    for (int o = 1; o < 32; o <<= 1) {
        const int nb = __shfl_up_sync(0xffffffffu, ex, o);
        if (lane >= o) ex += nb;
    }
    ex -= eqc;   // exclusive prefix over lanes

    int run = cnt_gt + ex;
#pragma unroll
    for (int i = 0; i < 8; i++) {
        const bool eq = (key[i] == T);
        if ((key[i] > T) || (eq && run < nn)) g_ind[lane * 8 + i] = 1.0f;
        run += eq;
    }
}

// ============================================================================
// Kernel 3: out[b,q,k,h] *= ind[k]  (2 float4/thread, batched loads, MLP=2;
//   both elements hit the same ind column: 65536 items ≡ 0 mod 256)
// ============================================================================
__global__ void apply_ind(float4* __restrict__ out4)
{
    const int i0 = blockIdx.x * blockDim.x + threadIdx.x;   // 0..131071
    float4 a = out4[i0];
    float4 b = out4[i0 + 131072];
    const float m = g_ind[(i0 >> 1) & (N_ - 1)];
    a.x *= m; a.y *= m; a.z *= m; a.w *= m;
    b.x *= m; b.y *= m; b.z *= m; b.w *= m;
    out4[i0] = a;
    out4[i0 + 131072] = b;
}

// ============================================================================
extern "C" void kernel_launch(void* const* d_in, const int* in_sizes, int n_in,
                              void* d_out, int out_size)
{
    (void)in_sizes; (void)n_in; (void)out_size;
    const ulonglong2* q2  = (const ulonglong2*)d_in[0];
    const ulonglong2* k2  = (const ulonglong2*)d_in[1];
    const float2*     sq  = (const float2*)d_in[2];
    const float2*     sk  = (const float2*)d_in[3];
    const float*      roi = (const float*)d_in[4];
    const float*      W   = (const float*)d_in[5];
    const float*      b   = (const float*)d_in[6];
    const int*        nn  = (const int*)d_in[7];
    float4* out4 = (float4*)d_out;

    cudaFuncSetAttribute(fused_main, cudaFuncAttributeMaxDynamicSharedMemorySize,
                         SMEM_TOTAL);

    reorg_w<<<16, 256>>>(W, b);
    fused_main<<<GRID_, 512, SMEM_TOTAL>>>(q2, k2, sq, sk, roi, out4);
    mark_topk<<<64, 256>>>(nn);                       // 512 warps = 512 rows
    apply_ind<<<512, 256>>>(out4);
}